// round 1
// baseline (speedup 1.0000x reference)
#include <cuda_runtime.h>
#include <cuda_bf16.h>
#include <math.h>

// ---------------- problem constants ----------------
#define BB   2
#define SS   4096
#define HH   1024
#define NKH  8
#define NVH  16
#define DK   64
#define DV   64
#define KEY_DIM   (NKH*DK)          // 512
#define VAL_DIM   (NVH*DV)          // 1024
#define CONV_DIM  (2*KEY_DIM+VAL_DIM) // 2048
#define KSZ  4
#define MM   (BB*SS)                // 8192 rows

// ---------------- scratch (static device mem; no allocs allowed) ----------------
__device__ float g_mixed[(size_t)MM*CONV_DIM];   // qkv projection
__device__ float g_conv [(size_t)MM*CONV_DIM];   // after conv+silu
__device__ float g_z    [(size_t)MM*VAL_DIM];
__device__ float g_gate [(size_t)MM*NVH];        // g (decay log)
__device__ float g_beta [(size_t)MM*NVH];
__device__ float g_o    [(size_t)MM*VAL_DIM];    // scan output
__device__ float g_h    [(size_t)MM*VAL_DIM];    // after gated rmsnorm

// ---------------- SGEMM: C[M,N] = A[M,K] * B[N,K]^T  (both K-major) ----------------
// 128x128 block, BK=8, 256 threads, 8x8 per-thread microtile.
__global__ void __launch_bounds__(256, 2) sgemm_tn_kernel(
    const float* __restrict__ A, const float* __restrict__ B, float* __restrict__ C,
    int M, int N, int K)
{
    __shared__ float As[8][128];
    __shared__ float Bs[8][128];
    const int tid  = threadIdx.x;
    const int bm   = blockIdx.y * 128;
    const int bn   = blockIdx.x * 128;
    const int lrow = tid >> 1;        // 0..127
    const int lk   = (tid & 1) * 4;   // 0 or 4
    const float* Ag = A + (size_t)(bm + lrow) * K + lk;
    const float* Bg = B + (size_t)(bn + lrow) * K + lk;
    const int tx = tid & 15;          // N direction
    const int ty = tid >> 4;          // M direction

    float acc[8][8];
#pragma unroll
    for (int i = 0; i < 8; i++)
#pragma unroll
        for (int j = 0; j < 8; j++) acc[i][j] = 0.f;

    for (int k0 = 0; k0 < K; k0 += 8) {
        float4 a4 = *(const float4*)(Ag + k0);
        float4 b4 = *(const float4*)(Bg + k0);
        __syncthreads();
        As[lk+0][lrow] = a4.x; As[lk+1][lrow] = a4.y;
        As[lk+2][lrow] = a4.z; As[lk+3][lrow] = a4.w;
        Bs[lk+0][lrow] = b4.x; Bs[lk+1][lrow] = b4.y;
        Bs[lk+2][lrow] = b4.z; Bs[lk+3][lrow] = b4.w;
        __syncthreads();
#pragma unroll
        for (int kk = 0; kk < 8; kk++) {
            float4 ar0 = *(const float4*)&As[kk][ty*8];
            float4 ar1 = *(const float4*)&As[kk][ty*8+4];
            float4 br0 = *(const float4*)&Bs[kk][tx*8];
            float4 br1 = *(const float4*)&Bs[kk][tx*8+4];
            float ar[8] = {ar0.x,ar0.y,ar0.z,ar0.w,ar1.x,ar1.y,ar1.z,ar1.w};
            float br[8] = {br0.x,br0.y,br0.z,br0.w,br1.x,br1.y,br1.z,br1.w};
#pragma unroll
            for (int i = 0; i < 8; i++)
#pragma unroll
                for (int j = 0; j < 8; j++)
                    acc[i][j] = fmaf(ar[i], br[j], acc[i][j]);
        }
    }
#pragma unroll
    for (int i = 0; i < 8; i++) {
        float* Cp = C + (size_t)(bm + ty*8 + i) * N + bn + tx*8;
        float4 c0 = make_float4(acc[i][0],acc[i][1],acc[i][2],acc[i][3]);
        float4 c1 = make_float4(acc[i][4],acc[i][5],acc[i][6],acc[i][7]);
        *(float4*)(Cp)     = c0;
        *(float4*)(Cp + 4) = c1;
    }
}

// ---------------- depthwise causal conv (k=4) + silu ----------------
__global__ void conv_silu_kernel(const float* __restrict__ mixed,
                                 const float* __restrict__ conv_w,
                                 float* __restrict__ out)
{
    size_t idx = (size_t)blockIdx.x * blockDim.x + threadIdx.x;
    if (idx >= (size_t)MM * CONV_DIM) return;
    int c  = (int)(idx & (CONV_DIM - 1));
    int bs = (int)(idx >> 11);
    int s  = bs & (SS - 1);
    float w0 = conv_w[c*4+0], w1 = conv_w[c*4+1], w2 = conv_w[c*4+2], w3 = conv_w[c*4+3];
    const float* p = mixed + idx;
    float acc = p[0] * w3;                       // tap j=3 -> x[s]
    if (s >= 1) acc = fmaf(p[-CONV_DIM],   w2, acc);
    if (s >= 2) acc = fmaf(p[-2*CONV_DIM], w1, acc);
    if (s >= 3) acc = fmaf(p[-3*CONV_DIM], w0, acc);
    out[idx] = acc / (1.f + expf(-acc));         // silu
}

// ---------------- small projections: a -> g(decay), b -> beta ----------------
// One block handles 16 rows. 256 threads: out = tid>>3 (0..15 -> W_a, 16..31 -> W_b),
// each output computed by 8 threads (128 K-elements each), shfl-reduced.
__global__ void proj_gate_kernel(const float* __restrict__ hidden,
                                 const float* __restrict__ W_b,
                                 const float* __restrict__ W_a,
                                 const float* __restrict__ dt_bias,
                                 const float* __restrict__ A_log,
                                 float* __restrict__ gg, float* __restrict__ gb)
{
    int m0  = blockIdx.x * 16;
    int out = threadIdx.x >> 3;     // 0..31
    int kp  = threadIdx.x & 7;
    int h   = out & 15;
    bool isA = (out < 16);
    const float4* Wp = (const float4*)(((isA ? W_a : W_b) + (size_t)h * HH) + kp * 128);
    for (int r = 0; r < 16; r++) {
        int m = m0 + r;
        const float4* hp = (const float4*)((hidden + (size_t)m * HH) + kp * 128);
        float s = 0.f;
#pragma unroll 8
        for (int k = 0; k < 32; k++) {
            float4 x = hp[k], w = Wp[k];
            s = fmaf(x.x, w.x, s); s = fmaf(x.y, w.y, s);
            s = fmaf(x.z, w.z, s); s = fmaf(x.w, w.w, s);
        }
        s += __shfl_xor_sync(0xffffffffu, s, 1);
        s += __shfl_xor_sync(0xffffffffu, s, 2);
        s += __shfl_xor_sync(0xffffffffu, s, 4);
        if (kp == 0) {
            size_t idx = (size_t)m * NVH + h;
            if (isA) {
                float x  = s + dt_bias[h];
                float sp = (x > 20.f) ? x : log1pf(expf(x));
                gg[idx]  = -expf(A_log[h]) * sp;
            } else {
                gb[idx]  = 1.f / (1.f + expf(-s));
            }
        }
    }
}

// ---------------- gated delta-rule scan ----------------
// Per-dv-column recurrences are independent. Grid: (b,h,grp) = 2*16*4 = 128 CTAs.
// 128 threads: 16 columns x 8 threads; each thread owns 8 state rows in registers.
// Dot reductions via shfl_xor 1,2,4 within aligned 8-lane groups.
struct ScanStep { float4 ka, kb, qa, qb; float v, g, b; };

__global__ void __launch_bounds__(128, 1) scan_kernel(
    const float* __restrict__ qkv,   // [b,s,2048] post conv+silu
    const float* __restrict__ gg,    // [b*s,16]
    const float* __restrict__ gb,    // [b*s,16]
    float* __restrict__ o_out)       // [b*s,1024]
{
    const int blk = blockIdx.x;
    const int bh  = blk >> 2;          // 0..31
    const int b   = bh >> 4;
    const int h   = bh & 15;
    const int grp = blk & 3;
    const int tid = threadIdx.x;
    const int col = grp * 16 + (tid >> 3);   // 0..63
    const int rp  = tid & 7;
    const int r0  = rp * 8;
    const int kq  = h >> 1;                  // GQA: repeat_interleave(2)

    const float* qbase = qkv + (size_t)b * SS * CONV_DIM + (size_t)kq * DK + r0;
    const float* kbase = qbase + KEY_DIM;
    const float* vbase = qkv + (size_t)b * SS * CONV_DIM + 2*KEY_DIM + h * DV + col;
    const float* gbase = gg + (size_t)b * SS * NVH + h;
    const float* bbase = gb + (size_t)b * SS * NVH + h;
    float*       obase = o_out + (size_t)b * SS * VAL_DIM + h * DV + col;

    float S[8];
#pragma unroll
    for (int i = 0; i < 8; i++) S[i] = 0.f;

    auto load = [&](ScanStep& p, int t) {
        size_t off = (size_t)t * CONV_DIM;
        p.ka = *(const float4*)(kbase + off);
        p.kb = *(const float4*)(kbase + off + 4);
        p.qa = *(const float4*)(qbase + off);
        p.qb = *(const float4*)(qbase + off + 4);
        p.v  = vbase[off];
        p.g  = gbase[(size_t)t * NVH];
        p.b  = bbase[(size_t)t * NVH];
    };

    auto compute = [&](const ScanStep& p, int t) {
        float eg = expf(p.g);
        float kr[8] = {p.ka.x,p.ka.y,p.ka.z,p.ka.w,p.kb.x,p.kb.y,p.kb.z,p.kb.w};
        float qr[8] = {p.qa.x,p.qa.y,p.qa.z,p.qa.w,p.qb.x,p.qb.y,p.qb.z,p.qb.w};
        float d0 = 0.f, d1 = 0.f;
#pragma unroll
        for (int i = 0; i < 8; i += 2) {
            d0 = fmaf(S[i],   kr[i],   d0);
            d1 = fmaf(S[i+1], kr[i+1], d1);
        }
        float d = d0 + d1;
        d += __shfl_xor_sync(0xffffffffu, d, 1);
        d += __shfl_xor_sync(0xffffffffu, d, 2);
        d += __shfl_xor_sync(0xffffffffu, d, 4);
        float delta = p.b * (p.v - eg * d);
        float o0 = 0.f, o1 = 0.f;
#pragma unroll
        for (int i = 0; i < 8; i++) {
            S[i] = fmaf(S[i], eg, kr[i] * delta);
            if (i & 1) o1 = fmaf(S[i], qr[i], o1);
            else       o0 = fmaf(S[i], qr[i], o0);
        }
        float op = o0 + o1;
        op += __shfl_xor_sync(0xffffffffu, op, 1);
        op += __shfl_xor_sync(0xffffffffu, op, 2);
        op += __shfl_xor_sync(0xffffffffu, op, 4);
        if (rp == 0) obase[(size_t)t * VAL_DIM] = op * 0.125f;  // q * DK^-0.5
    };

    // 4-slot software pipeline (prefetch distance ~3 steps > L2 latency)
    ScanStep p0, p1, p2, p3;
    load(p0, 0); load(p1, 1); load(p2, 2); load(p3, 3);
    for (int t = 0; t < SS; t += 4) {
        compute(p0, t);   if (t + 4 < SS) load(p0, t + 4);
        compute(p1, t+1); if (t + 5 < SS) load(p1, t + 5);
        compute(p2, t+2); if (t + 6 < SS) load(p2, t + 6);
        compute(p3, t+3); if (t + 7 < SS) load(p3, t + 7);
    }
}

// ---------------- gated RMSNorm: h = (o*silu(z)) * rsqrt(mean sq + eps) * w ----------------
__global__ void gated_norm_kernel(const float* __restrict__ o,
                                  const float* __restrict__ z,
                                  const float* __restrict__ nw,
                                  float* __restrict__ hout)
{
    int warp = threadIdx.x >> 5, lane = threadIdx.x & 31;
    size_t idx = (size_t)blockIdx.x * 8 + warp;          // (bs,h) pair, 131072 total
    size_t base = idx * DV;
    float o0 = o[base + lane],      o1 = o[base + lane + 32];
    float z0 = z[base + lane],      z1 = z[base + lane + 32];
    float h0 = o0 * (z0 / (1.f + expf(-z0)));
    float h1 = o1 * (z1 / (1.f + expf(-z1)));
    float ss = h0*h0 + h1*h1;
#pragma unroll
    for (int off = 16; off > 0; off >>= 1)
        ss += __shfl_xor_sync(0xffffffffu, ss, off);
    float scale = rsqrtf(ss * (1.f / DV) + 1e-6f);
    hout[base + lane]      = h0 * scale * nw[lane];
    hout[base + lane + 32] = h1 * scale * nw[lane + 32];
}

// ---------------- driver ----------------
extern "C" void kernel_launch(void* const* d_in, const int* in_sizes, int n_in,
                              void* d_out, int out_size)
{
    const float* hidden  = (const float*)d_in[0];
    const float* W_qkv   = (const float*)d_in[1];
    const float* conv_w  = (const float*)d_in[2];
    const float* W_z     = (const float*)d_in[3];
    const float* W_b     = (const float*)d_in[4];
    const float* W_a     = (const float*)d_in[5];
    const float* dt_bias = (const float*)d_in[6];
    const float* A_log   = (const float*)d_in[7];
    const float* norm_w  = (const float*)d_in[8];
    const float* W_out   = (const float*)d_in[9];
    float* out = (float*)d_out;

    float *mixed, *conv, *z, *gg, *gb, *ov, *hh;
    cudaGetSymbolAddress((void**)&mixed, g_mixed);
    cudaGetSymbolAddress((void**)&conv,  g_conv);
    cudaGetSymbolAddress((void**)&z,     g_z);
    cudaGetSymbolAddress((void**)&gg,    g_gate);
    cudaGetSymbolAddress((void**)&gb,    g_beta);
    cudaGetSymbolAddress((void**)&ov,    g_o);
    cudaGetSymbolAddress((void**)&hh,    g_h);

    // 1) mixed = hidden @ W_qkv^T   [8192,2048]
    sgemm_tn_kernel<<<dim3(CONV_DIM/128, MM/128), 256>>>(hidden, W_qkv, mixed, MM, CONV_DIM, HH);
    // 2) depthwise causal conv + silu
    {
        size_t n = (size_t)MM * CONV_DIM;
        conv_silu_kernel<<<(unsigned)((n + 255) / 256), 256>>>(mixed, conv_w, conv);
    }
    // 3) z = hidden @ W_z^T        [8192,1024]
    sgemm_tn_kernel<<<dim3(VAL_DIM/128, MM/128), 256>>>(hidden, W_z, z, MM, VAL_DIM, HH);
    // 4) gate / beta projections
    proj_gate_kernel<<<MM/16, 256>>>(hidden, W_b, W_a, dt_bias, A_log, gg, gb);
    // 5) gated delta-rule scan
    scan_kernel<<<BB*NVH*4, 128>>>(conv, gg, gb, ov);
    // 6) gated RMSNorm
    gated_norm_kernel<<<(MM*NVH)/8, 256>>>(ov, z, norm_w, hh);
    // 7) out = h @ W_out^T         [8192,1024]
    sgemm_tn_kernel<<<dim3(HH/128, MM/128), 256>>>(hh, W_out, out, MM, HH, VAL_DIM);
}

// round 2
// speedup vs baseline: 1.1992x; 1.1992x over previous
#include <cuda_runtime.h>
#include <cuda_bf16.h>
#include <math.h>

// ---------------- problem constants ----------------
#define BB   2
#define SS   4096
#define HH   1024
#define NKH  8
#define NVH  16
#define DK   64
#define DV   64
#define KEY_DIM   (NKH*DK)            // 512
#define VAL_DIM   (NVH*DV)            // 1024
#define CONV_DIM  (2*KEY_DIM+VAL_DIM) // 2048
#define KSZ  4
#define MM   (BB*SS)                  // 8192 rows
#define NCAT 3200                     // 2048 qkv + 1024 z + 16 a + 16 b + 96 pad

// ---------------- scratch (static device mem; no allocs allowed) ----------------
__device__ float g_wcat [(size_t)NCAT*HH];       // packed weights
__device__ float g_ccat [(size_t)MM*NCAT];       // fused projection output
__device__ float g_conv [(size_t)MM*CONV_DIM];   // after conv+silu
__device__ float g_gate [(size_t)MM*NVH];        // g (decay log)
__device__ float g_beta [(size_t)MM*NVH];
__device__ float g_o    [(size_t)MM*VAL_DIM];    // scan output
__device__ float g_h    [(size_t)MM*VAL_DIM];    // after gated rmsnorm

// ---------------- weight pack: Wcat = [W_qkv; W_z; W_a; W_b; 0pad] ----------------
__global__ void pack_w_kernel(const float* __restrict__ Wqkv, const float* __restrict__ Wz,
                              const float* __restrict__ Wa,   const float* __restrict__ Wb,
                              float* __restrict__ Wcat)
{
    int idx = blockIdx.x * blockDim.x + threadIdx.x;      // float4 index
    const int HV4 = HH / 4;
    if (idx >= NCAT * HV4) return;
    int row = idx / HV4;
    int c4  = idx - row * HV4;
    float4 v = make_float4(0.f, 0.f, 0.f, 0.f);
    if      (row < 2048) v = ((const float4*)Wqkv)[(size_t)row * HV4 + c4];
    else if (row < 3072) v = ((const float4*)Wz  )[(size_t)(row - 2048) * HV4 + c4];
    else if (row < 3088) v = ((const float4*)Wa  )[(size_t)(row - 3072) * HV4 + c4];
    else if (row < 3104) v = ((const float4*)Wb  )[(size_t)(row - 3088) * HV4 + c4];
    ((float4*)Wcat)[idx] = v;
}

// ---------------- SGEMM: C[M,N] = A[M,K] * B[N,K]^T, double-buffered smem ----------------
__global__ void __launch_bounds__(256, 2) sgemm_tn_kernel(
    const float* __restrict__ A, const float* __restrict__ B, float* __restrict__ C,
    int M, int N, int K)
{
    __shared__ float As[2][8][128];
    __shared__ float Bs[2][8][128];
    const int tid  = threadIdx.x;
    const int bm   = blockIdx.y * 128;
    const int bn   = blockIdx.x * 128;
    const int lrow = tid >> 1;        // 0..127
    const int lk   = (tid & 1) * 4;   // 0 or 4
    const float* Ag = A + (size_t)(bm + lrow) * K + lk;
    const float* Bg = B + (size_t)(bn + lrow) * K + lk;
    const int tx = tid & 15;          // N direction
    const int ty = tid >> 4;          // M direction

    float acc[8][8];
#pragma unroll
    for (int i = 0; i < 8; i++)
#pragma unroll
        for (int j = 0; j < 8; j++) acc[i][j] = 0.f;

    // prologue: fill buffer 0
    {
        float4 a4 = *(const float4*)(Ag);
        float4 b4 = *(const float4*)(Bg);
        As[0][lk+0][lrow] = a4.x; As[0][lk+1][lrow] = a4.y;
        As[0][lk+2][lrow] = a4.z; As[0][lk+3][lrow] = a4.w;
        Bs[0][lk+0][lrow] = b4.x; Bs[0][lk+1][lrow] = b4.y;
        Bs[0][lk+2][lrow] = b4.z; Bs[0][lk+3][lrow] = b4.w;
    }
    __syncthreads();

    int buf = 0;
    for (int k0 = 8; ; k0 += 8) {
        const bool more = (k0 < K);
        float4 na, nb;
        if (more) {
            na = *(const float4*)(Ag + k0);
            nb = *(const float4*)(Bg + k0);
        }
#pragma unroll
        for (int kk = 0; kk < 8; kk++) {
            float4 ar0 = *(const float4*)&As[buf][kk][ty*8];
            float4 ar1 = *(const float4*)&As[buf][kk][ty*8+4];
            float4 br0 = *(const float4*)&Bs[buf][kk][tx*8];
            float4 br1 = *(const float4*)&Bs[buf][kk][tx*8+4];
            float ar[8] = {ar0.x,ar0.y,ar0.z,ar0.w,ar1.x,ar1.y,ar1.z,ar1.w};
            float br[8] = {br0.x,br0.y,br0.z,br0.w,br1.x,br1.y,br1.z,br1.w};
#pragma unroll
            for (int i = 0; i < 8; i++)
#pragma unroll
                for (int j = 0; j < 8; j++)
                    acc[i][j] = fmaf(ar[i], br[j], acc[i][j]);
        }
        if (!more) break;
        const int nb_ = buf ^ 1;
        As[nb_][lk+0][lrow] = na.x; As[nb_][lk+1][lrow] = na.y;
        As[nb_][lk+2][lrow] = na.z; As[nb_][lk+3][lrow] = na.w;
        Bs[nb_][lk+0][lrow] = nb.x; Bs[nb_][lk+1][lrow] = nb.y;
        Bs[nb_][lk+2][lrow] = nb.z; Bs[nb_][lk+3][lrow] = nb.w;
        __syncthreads();
        buf = nb_;
    }

#pragma unroll
    for (int i = 0; i < 8; i++) {
        float* Cp = C + (size_t)(bm + ty*8 + i) * N + bn + tx*8;
        *(float4*)(Cp)     = make_float4(acc[i][0],acc[i][1],acc[i][2],acc[i][3]);
        *(float4*)(Cp + 4) = make_float4(acc[i][4],acc[i][5],acc[i][6],acc[i][7]);
    }
}

// ---------------- depthwise causal conv (k=4) + silu (reads Ccat, writes compact) ----------------
__global__ void conv_silu_kernel(const float* __restrict__ ccat,
                                 const float* __restrict__ conv_w,
                                 float* __restrict__ out)
{
    size_t idx = (size_t)blockIdx.x * blockDim.x + threadIdx.x;
    if (idx >= (size_t)MM * CONV_DIM) return;
    int c  = (int)(idx & (CONV_DIM - 1));
    int bs = (int)(idx >> 11);
    int s  = bs & (SS - 1);
    float w0 = conv_w[c*4+0], w1 = conv_w[c*4+1], w2 = conv_w[c*4+2], w3 = conv_w[c*4+3];
    const float* p = ccat + (size_t)bs * NCAT + c;
    float acc = p[0] * w3;                          // tap j=3 -> x[s]
    if (s >= 1) acc = fmaf(p[-NCAT],   w2, acc);
    if (s >= 2) acc = fmaf(p[-2*NCAT], w1, acc);
    if (s >= 3) acc = fmaf(p[-3*NCAT], w0, acc);
    out[idx] = acc / (1.f + expf(-acc));            // silu
}

// ---------------- gate epilogue: g = -exp(A_log)*softplus(a+dt), beta = sigmoid(b) ----------------
__global__ void gate_kernel(const float* __restrict__ ccat,
                            const float* __restrict__ dt_bias,
                            const float* __restrict__ A_log,
                            float* __restrict__ gg, float* __restrict__ gb)
{
    int idx = blockIdx.x * blockDim.x + threadIdx.x;   // m*16 + h
    if (idx >= MM * NVH) return;
    int h = idx & 15;
    int m = idx >> 4;
    float a = ccat[(size_t)m * NCAT + 3072 + h];
    float b = ccat[(size_t)m * NCAT + 3088 + h];
    float x  = a + dt_bias[h];
    float sp = (x > 20.f) ? x : log1pf(expf(x));
    gg[idx]  = -expf(A_log[h]) * sp;
    gb[idx]  = 1.f / (1.f + expf(-b));
}

// ---------------- gated delta-rule scan ----------------
struct ScanStep { float4 ka, kb, qa, qb; float v, g, b; };

__global__ void __launch_bounds__(128, 1) scan_kernel(
    const float* __restrict__ qkv,   // [b,s,2048] post conv+silu
    const float* __restrict__ gg,    // [b*s,16]
    const float* __restrict__ gb,    // [b*s,16]
    float* __restrict__ o_out)       // [b*s,1024]
{
    const int blk = blockIdx.x;
    const int bh  = blk >> 2;          // 0..31
    const int b   = bh >> 4;
    const int h   = bh & 15;
    const int grp = blk & 3;
    const int tid = threadIdx.x;
    const int col = grp * 16 + (tid >> 3);   // 0..63
    const int rp  = tid & 7;
    const int r0  = rp * 8;
    const int kq  = h >> 1;                  // GQA: repeat_interleave(2)

    const float* qbase = qkv + (size_t)b * SS * CONV_DIM + (size_t)kq * DK + r0;
    const float* kbase = qbase + KEY_DIM;
    const float* vbase = qkv + (size_t)b * SS * CONV_DIM + 2*KEY_DIM + h * DV + col;
    const float* gbase = gg + (size_t)b * SS * NVH + h;
    const float* bbase = gb + (size_t)b * SS * NVH + h;
    float*       obase = o_out + (size_t)b * SS * VAL_DIM + h * DV + col;

    float S[8];
#pragma unroll
    for (int i = 0; i < 8; i++) S[i] = 0.f;

    auto load = [&](ScanStep& p, int t) {
        size_t off = (size_t)t * CONV_DIM;
        p.ka = *(const float4*)(kbase + off);
        p.kb = *(const float4*)(kbase + off + 4);
        p.qa = *(const float4*)(qbase + off);
        p.qb = *(const float4*)(qbase + off + 4);
        p.v  = vbase[off];
        p.g  = gbase[(size_t)t * NVH];
        p.b  = bbase[(size_t)t * NVH];
    };

    auto compute = [&](const ScanStep& p, int t) {
        float eg = expf(p.g);
        float kr[8] = {p.ka.x,p.ka.y,p.ka.z,p.ka.w,p.kb.x,p.kb.y,p.kb.z,p.kb.w};
        float qr[8] = {p.qa.x,p.qa.y,p.qa.z,p.qa.w,p.qb.x,p.qb.y,p.qb.z,p.qb.w};
        float d0 = 0.f, d1 = 0.f;
#pragma unroll
        for (int i = 0; i < 8; i += 2) {
            d0 = fmaf(S[i],   kr[i],   d0);
            d1 = fmaf(S[i+1], kr[i+1], d1);
        }
        float d = d0 + d1;
        d += __shfl_xor_sync(0xffffffffu, d, 1);
        d += __shfl_xor_sync(0xffffffffu, d, 2);
        d += __shfl_xor_sync(0xffffffffu, d, 4);
        float delta = p.b * (p.v - eg * d);
        float o0 = 0.f, o1 = 0.f;
#pragma unroll
        for (int i = 0; i < 8; i++) {
            S[i] = fmaf(S[i], eg, kr[i] * delta);
            if (i & 1) o1 = fmaf(S[i], qr[i], o1);
            else       o0 = fmaf(S[i], qr[i], o0);
        }
        float op = o0 + o1;
        op += __shfl_xor_sync(0xffffffffu, op, 1);
        op += __shfl_xor_sync(0xffffffffu, op, 2);
        op += __shfl_xor_sync(0xffffffffu, op, 4);
        if (rp == 0) obase[(size_t)t * VAL_DIM] = op * 0.125f;  // q * DK^-0.5
    };

    ScanStep p0, p1, p2, p3;
    load(p0, 0); load(p1, 1); load(p2, 2); load(p3, 3);
    for (int t = 0; t < SS; t += 4) {
        compute(p0, t);   if (t + 4 < SS) load(p0, t + 4);
        compute(p1, t+1); if (t + 5 < SS) load(p1, t + 5);
        compute(p2, t+2); if (t + 6 < SS) load(p2, t + 6);
        compute(p3, t+3); if (t + 7 < SS) load(p3, t + 7);
    }
}

// ---------------- gated RMSNorm: h = (o*silu(z)) * rsqrt(mean sq + eps) * w ----------------
__global__ void gated_norm_kernel(const float* __restrict__ o,
                                  const float* __restrict__ ccat,   // z lives at cols [2048,3072)
                                  const float* __restrict__ nw,
                                  float* __restrict__ hout)
{
    int warp = threadIdx.x >> 5, lane = threadIdx.x & 31;
    size_t idx = (size_t)blockIdx.x * 8 + warp;          // (bs,h) pair, 131072 total
    int m  = (int)(idx >> 4);
    int hd = (int)(idx & 15);
    size_t base  = idx * DV;
    size_t zbase = (size_t)m * NCAT + 2048 + hd * DV;
    float o0 = o[base + lane],       o1 = o[base + lane + 32];
    float z0 = ccat[zbase + lane],   z1 = ccat[zbase + lane + 32];
    float h0 = o0 * (z0 / (1.f + expf(-z0)));
    float h1 = o1 * (z1 / (1.f + expf(-z1)));
    float ss = h0*h0 + h1*h1;
#pragma unroll
    for (int off = 16; off > 0; off >>= 1)
        ss += __shfl_xor_sync(0xffffffffu, ss, off);
    float scale = rsqrtf(ss * (1.f / DV) + 1e-6f);
    hout[base + lane]      = h0 * scale * nw[lane];
    hout[base + lane + 32] = h1 * scale * nw[lane + 32];
}

// ---------------- driver ----------------
extern "C" void kernel_launch(void* const* d_in, const int* in_sizes, int n_in,
                              void* d_out, int out_size)
{
    const float* hidden  = (const float*)d_in[0];
    const float* W_qkv   = (const float*)d_in[1];
    const float* conv_w  = (const float*)d_in[2];
    const float* W_z     = (const float*)d_in[3];
    const float* W_b     = (const float*)d_in[4];
    const float* W_a     = (const float*)d_in[5];
    const float* dt_bias = (const float*)d_in[6];
    const float* A_log   = (const float*)d_in[7];
    const float* norm_w  = (const float*)d_in[8];
    const float* W_out   = (const float*)d_in[9];
    float* out = (float*)d_out;

    float *wcat, *ccat, *conv, *gg, *gb, *ov, *hh;
    cudaGetSymbolAddress((void**)&wcat, g_wcat);
    cudaGetSymbolAddress((void**)&ccat, g_ccat);
    cudaGetSymbolAddress((void**)&conv, g_conv);
    cudaGetSymbolAddress((void**)&gg,   g_gate);
    cudaGetSymbolAddress((void**)&gb,   g_beta);
    cudaGetSymbolAddress((void**)&ov,   g_o);
    cudaGetSymbolAddress((void**)&hh,   g_h);

    // 0) pack weights into Wcat [3200, 1024]
    {
        int n4 = NCAT * (HH / 4);
        pack_w_kernel<<<(n4 + 255) / 256, 256>>>(W_qkv, W_z, W_a, W_b, wcat);
    }
    // 1) Ccat = hidden @ Wcat^T   [8192, 3200]  (qkv | z | a | b | pad)
    sgemm_tn_kernel<<<dim3(NCAT/128, MM/128), 256>>>(hidden, wcat, ccat, MM, NCAT, HH);
    // 2) depthwise causal conv + silu on qkv columns
    {
        size_t n = (size_t)MM * CONV_DIM;
        conv_silu_kernel<<<(unsigned)((n + 255) / 256), 256>>>(ccat, conv_w, conv);
    }
    // 3) gate / beta from a,b columns
    gate_kernel<<<(MM*NVH + 255) / 256, 256>>>(ccat, dt_bias, A_log, gg, gb);
    // 4) gated delta-rule scan
    scan_kernel<<<BB*NVH*4, 128>>>(conv, gg, gb, ov);
    // 5) gated RMSNorm (z read from Ccat)
    gated_norm_kernel<<<(MM*NVH)/8, 256>>>(ov, ccat, norm_w, hh);
    // 6) out = h @ W_out^T         [8192, 1024]
    sgemm_tn_kernel<<<dim3(HH/128, MM/128), 256>>>(hh, W_out, out, MM, HH, VAL_DIM);
}

// round 5
// speedup vs baseline: 1.5515x; 1.2937x over previous
#include <cuda_runtime.h>
#include <cuda_bf16.h>
#include <math.h>
#include <stdint.h>

// ---------------- problem constants ----------------
#define BB   2
#define SS   4096
#define HH   1024
#define NKH  8
#define NVH  16
#define DK   64
#define DV   64
#define KEY_DIM   (NKH*DK)            // 512
#define VAL_DIM   (NVH*DV)            // 1024
#define CONV_DIM  (2*KEY_DIM+VAL_DIM) // 2048
#define MM   (BB*SS)                  // 8192 rows
#define NCAT 3200                     // 2048 qkv + 1024 z + 16 a + 16 b + 96 pad
#define GK   3072                     // split-bf16 K' = 3*1024
#define KCHUNKS (GK/32)               // 96

// ---------------- scratch (static device mem; no allocs allowed) ----------------
__device__ __nv_bfloat16 g_ahl  [(size_t)MM*GK];     // hidden split [hi|hi|lo]
__device__ __nv_bfloat16 g_w16  [(size_t)NCAT*GK];   // packed weights split [hi|lo|hi]
__device__ __nv_bfloat16 g_wo16 [(size_t)HH*GK];     // W_out split [hi|lo|hi]
__device__ __nv_bfloat16 g_hhl  [(size_t)MM*GK];     // normed h split [hi|hi|lo]
__device__ float g_ccat [(size_t)MM*NCAT];           // fused projection output
__device__ float g_conv [(size_t)MM*CONV_DIM];       // after conv+silu
__device__ float g_gate [(size_t)MM*NVH];
__device__ float g_beta [(size_t)MM*NVH];
__device__ float g_o    [(size_t)MM*VAL_DIM];        // scan output

// ================= helpers =================
__device__ __forceinline__ uint32_t smem_u32(const void* p) {
    uint32_t a;
    asm("{ .reg .u64 t; cvta.to.shared.u64 t, %1; cvt.u32.u64 %0, t; }" : "=r"(a) : "l"(p));
    return a;
}
__device__ __forceinline__ void ldsm_x4(uint32_t& r0, uint32_t& r1, uint32_t& r2, uint32_t& r3, uint32_t addr) {
    asm volatile("ldmatrix.sync.aligned.m8n8.x4.shared.b16 {%0,%1,%2,%3}, [%4];"
                 : "=r"(r0), "=r"(r1), "=r"(r2), "=r"(r3) : "r"(addr));
}
__device__ __forceinline__ void ldsm_x2(uint32_t& r0, uint32_t& r1, uint32_t addr) {
    asm volatile("ldmatrix.sync.aligned.m8n8.x2.shared.b16 {%0,%1}, [%2];"
                 : "=r"(r0), "=r"(r1) : "r"(addr));
}
__device__ __forceinline__ void mma16816(float* c, uint32_t a0, uint32_t a1, uint32_t a2, uint32_t a3,
                                         uint32_t b0, uint32_t b1) {
    asm volatile("mma.sync.aligned.m16n8k16.row.col.f32.bf16.bf16.f32 "
                 "{%0,%1,%2,%3}, {%4,%5,%6,%7}, {%8,%9}, {%0,%1,%2,%3};"
                 : "+f"(c[0]), "+f"(c[1]), "+f"(c[2]), "+f"(c[3])
                 : "r"(a0), "r"(a1), "r"(a2), "r"(a3), "r"(b0), "r"(b1));
}

// ================= split-bf16 conversion kernels =================
// A-side layout: [hi | hi | lo] along K' ; B-side: [hi | lo | hi]
__global__ void cvt_hidden_kernel(const float* __restrict__ x, __nv_bfloat16* __restrict__ out)
{
    int idx = blockIdx.x * blockDim.x + threadIdx.x;
    if (idx >= MM * HH) return;
    int m = idx >> 10, k = idx & 1023;
    float v = x[idx];
    __nv_bfloat16 hi = __float2bfloat16_rn(v);
    __nv_bfloat16 lo = __float2bfloat16_rn(v - __bfloat162float(hi));
    size_t base = (size_t)m * GK + k;
    out[base] = hi; out[base + 1024] = hi; out[base + 2048] = lo;
}
__global__ void cvt_w_kernel(const float* __restrict__ Wqkv, const float* __restrict__ Wz,
                             const float* __restrict__ Wa,   const float* __restrict__ Wb,
                             __nv_bfloat16* __restrict__ out)
{
    int idx = blockIdx.x * blockDim.x + threadIdx.x;
    if (idx >= NCAT * HH) return;
    int r = idx >> 10, k = idx & 1023;
    float v = 0.f;
    if      (r < 2048) v = Wqkv[(size_t)r * HH + k];
    else if (r < 3072) v = Wz  [(size_t)(r - 2048) * HH + k];
    else if (r < 3088) v = Wa  [(size_t)(r - 3072) * HH + k];
    else if (r < 3104) v = Wb  [(size_t)(r - 3088) * HH + k];
    __nv_bfloat16 hi = __float2bfloat16_rn(v);
    __nv_bfloat16 lo = __float2bfloat16_rn(v - __bfloat162float(hi));
    size_t base = (size_t)r * GK + k;
    out[base] = hi; out[base + 1024] = lo; out[base + 2048] = hi;
}
__global__ void cvt_wout_kernel(const float* __restrict__ W, __nv_bfloat16* __restrict__ out)
{
    int idx = blockIdx.x * blockDim.x + threadIdx.x;
    if (idx >= HH * VAL_DIM) return;
    int r = idx >> 10, k = idx & 1023;
    float v = W[idx];
    __nv_bfloat16 hi = __float2bfloat16_rn(v);
    __nv_bfloat16 lo = __float2bfloat16_rn(v - __bfloat162float(hi));
    size_t base = (size_t)r * GK + k;
    out[base] = hi; out[base + 1024] = lo; out[base + 2048] = hi;
}

// ================= HMMA GEMM: C[M,N] = A'[M,GK] * B'[N,GK]^T (bf16 in, fp32 out) =================
// CTA tile 128x128, BK=32, 8 warps in 2(M) x 4(N), warp tile 64x32, m16n8k16.
// SMEM row pitch 40 bf16 (80B) -> conflict-free ldmatrix.
#define SPITCH 40

__global__ void __launch_bounds__(256) mma_gemm_kernel(
    const __nv_bfloat16* __restrict__ A, const __nv_bfloat16* __restrict__ B,
    float* __restrict__ C, int N)
{
    __shared__ __nv_bfloat16 As[2][128 * SPITCH];
    __shared__ __nv_bfloat16 Bs[2][128 * SPITCH];

    const int tid  = threadIdx.x;
    const int lane = tid & 31;
    const int wid  = tid >> 5;
    const int warpM = wid & 1;           // 0..1
    const int warpN = wid >> 1;          // 0..3
    const int bm = blockIdx.y * 128;
    const int bn = blockIdx.x * 128;

    // global load mapping: thread t -> row t/2, half t%2 (32B = 16 bf16)
    const int grow = tid >> 1;
    const int ghalf = tid & 1;
    const __nv_bfloat16* Ag = A + (size_t)(bm + grow) * GK + ghalf * 16;
    const __nv_bfloat16* Bg = B + (size_t)(bn + grow) * GK + ghalf * 16;
    const uint32_t aB = smem_u32(As);
    const uint32_t bB = smem_u32(Bs);
    const uint32_t stoff = grow * (SPITCH * 2) + ghalf * 32;   // byte offset

    // ldmatrix addresses (byte offsets within a buffer)
    // A frag (mi, kk): row = warpM*64 + mi*16 + (lane&15); col = kk*16 + (lane>>4)*8
    const uint32_t aRow = warpM * 64 + (lane & 15);
    const uint32_t aCol = (lane >> 4) * 8;
    // B frag (nj, kk): row = warpN*32 + nj*8 + (lane&7); col = kk*16 + ((lane&15)>>3)*8
    const uint32_t bRow = warpN * 32 + (lane & 7);
    const uint32_t bCol = ((lane & 15) >> 3) * 8;

    float acc[4][4][4];
#pragma unroll
    for (int i = 0; i < 4; i++)
#pragma unroll
        for (int j = 0; j < 4; j++)
#pragma unroll
            for (int x = 0; x < 4; x++) acc[i][j][x] = 0.f;

    // prologue: chunk 0 -> buf 0
    {
        uint4 a0 = *(const uint4*)(Ag);
        uint4 a1 = *(const uint4*)(Ag + 8);
        uint4 b0 = *(const uint4*)(Bg);
        uint4 b1 = *(const uint4*)(Bg + 8);
        *(uint4*)((char*)As[0] + stoff)      = a0;
        *(uint4*)((char*)As[0] + stoff + 16) = a1;
        *(uint4*)((char*)Bs[0] + stoff)      = b0;
        *(uint4*)((char*)Bs[0] + stoff + 16) = b1;
    }
    __syncthreads();

    for (int c = 0; c < KCHUNKS; c++) {
        const int buf = c & 1;
        uint4 na0, na1, nb0, nb1;
        const bool more = (c + 1 < KCHUNKS);
        if (more) {
            na0 = *(const uint4*)(Ag + (c + 1) * 32);
            na1 = *(const uint4*)(Ag + (c + 1) * 32 + 8);
            nb0 = *(const uint4*)(Bg + (c + 1) * 32);
            nb1 = *(const uint4*)(Bg + (c + 1) * 32 + 8);
        }

        const uint32_t aBuf = aB + buf * (128 * SPITCH * 2);
        const uint32_t bBuf = bB + buf * (128 * SPITCH * 2);
#pragma unroll
        for (int kk = 0; kk < 2; kk++) {
            uint32_t af[4][4], bf[4][2];
#pragma unroll
            for (int mi = 0; mi < 4; mi++) {
                uint32_t addr = aBuf + (aRow + mi * 16) * (SPITCH * 2) + (kk * 16 + aCol) * 2;
                ldsm_x4(af[mi][0], af[mi][1], af[mi][2], af[mi][3], addr);
            }
#pragma unroll
            for (int nj = 0; nj < 4; nj++) {
                uint32_t addr = bBuf + (bRow + nj * 8) * (SPITCH * 2) + (kk * 16 + bCol) * 2;
                ldsm_x2(bf[nj][0], bf[nj][1], addr);
            }
#pragma unroll
            for (int mi = 0; mi < 4; mi++)
#pragma unroll
                for (int nj = 0; nj < 4; nj++)
                    mma16816(acc[mi][nj], af[mi][0], af[mi][1], af[mi][2], af[mi][3],
                             bf[nj][0], bf[nj][1]);
        }

        if (more) {
            const int nbuf = buf ^ 1;
            *(uint4*)((char*)As[nbuf] + stoff)      = na0;
            *(uint4*)((char*)As[nbuf] + stoff + 16) = na1;
            *(uint4*)((char*)Bs[nbuf] + stoff)      = nb0;
            *(uint4*)((char*)Bs[nbuf] + stoff + 16) = nb1;
            __syncthreads();
        }
    }

    // epilogue: acc frag (mi,nj): c0,c1 -> row lane/4, cols (lane%4)*2; c2,c3 -> row+8
    const int erow = bm + warpM * 64 + (lane >> 2);
    const int ecol = bn + warpN * 32 + (lane & 3) * 2;
#pragma unroll
    for (int mi = 0; mi < 4; mi++) {
#pragma unroll
        for (int nj = 0; nj < 4; nj++) {
            float* C0 = C + (size_t)(erow + mi * 16) * N + ecol + nj * 8;
            float* C1 = C + (size_t)(erow + mi * 16 + 8) * N + ecol + nj * 8;
            *(float2*)C0 = make_float2(acc[mi][nj][0], acc[mi][nj][1]);
            *(float2*)C1 = make_float2(acc[mi][nj][2], acc[mi][nj][3]);
        }
    }
}

// ---------------- depthwise causal conv (k=4) + silu ----------------
__global__ void conv_silu_kernel(const float* __restrict__ ccat,
                                 const float* __restrict__ conv_w,
                                 float* __restrict__ out)
{
    size_t idx = (size_t)blockIdx.x * blockDim.x + threadIdx.x;
    if (idx >= (size_t)MM * CONV_DIM) return;
    int c  = (int)(idx & (CONV_DIM - 1));
    int bs = (int)(idx >> 11);
    int s  = bs & (SS - 1);
    float w0 = conv_w[c*4+0], w1 = conv_w[c*4+1], w2 = conv_w[c*4+2], w3 = conv_w[c*4+3];
    const float* p = ccat + (size_t)bs * NCAT + c;
    float acc = p[0] * w3;
    if (s >= 1) acc = fmaf(p[-NCAT],   w2, acc);
    if (s >= 2) acc = fmaf(p[-2*NCAT], w1, acc);
    if (s >= 3) acc = fmaf(p[-3*NCAT], w0, acc);
    out[idx] = acc / (1.f + expf(-acc));
}

// ---------------- gate epilogue ----------------
__global__ void gate_kernel(const float* __restrict__ ccat,
                            const float* __restrict__ dt_bias,
                            const float* __restrict__ A_log,
                            float* __restrict__ gg, float* __restrict__ gb)
{
    int idx = blockIdx.x * blockDim.x + threadIdx.x;
    if (idx >= MM * NVH) return;
    int h = idx & 15;
    int m = idx >> 4;
    float a = ccat[(size_t)m * NCAT + 3072 + h];
    float b = ccat[(size_t)m * NCAT + 3088 + h];
    float x  = a + dt_bias[h];
    float sp = (x > 20.f) ? x : log1pf(expf(x));
    gg[idx]  = -expf(A_log[h]) * sp;
    gb[idx]  = 1.f / (1.f + expf(-b));
}

// ---------------- gated delta-rule scan ----------------
struct ScanStep { float4 ka, kb, qa, qb; float v, g, b; };

__global__ void __launch_bounds__(128, 1) scan_kernel(
    const float* __restrict__ qkv, const float* __restrict__ gg,
    const float* __restrict__ gb,  float* __restrict__ o_out)
{
    const int blk = blockIdx.x;
    const int bh  = blk >> 2;
    const int b   = bh >> 4;
    const int h   = bh & 15;
    const int grp = blk & 3;
    const int tid = threadIdx.x;
    const int col = grp * 16 + (tid >> 3);
    const int rp  = tid & 7;
    const int r0  = rp * 8;
    const int kq  = h >> 1;

    const float* qbase = qkv + (size_t)b * SS * CONV_DIM + (size_t)kq * DK + r0;
    const float* kbase = qbase + KEY_DIM;
    const float* vbase = qkv + (size_t)b * SS * CONV_DIM + 2*KEY_DIM + h * DV + col;
    const float* gbase = gg + (size_t)b * SS * NVH + h;
    const float* bbase = gb + (size_t)b * SS * NVH + h;
    float*       obase = o_out + (size_t)b * SS * VAL_DIM + h * DV + col;

    float S[8];
#pragma unroll
    for (int i = 0; i < 8; i++) S[i] = 0.f;

    auto load = [&](ScanStep& p, int t) {
        size_t off = (size_t)t * CONV_DIM;
        p.ka = *(const float4*)(kbase + off);
        p.kb = *(const float4*)(kbase + off + 4);
        p.qa = *(const float4*)(qbase + off);
        p.qb = *(const float4*)(qbase + off + 4);
        p.v  = vbase[off];
        p.g  = gbase[(size_t)t * NVH];
        p.b  = bbase[(size_t)t * NVH];
    };

    auto compute = [&](const ScanStep& p, int t) {
        float eg = expf(p.g);
        float kr[8] = {p.ka.x,p.ka.y,p.ka.z,p.ka.w,p.kb.x,p.kb.y,p.kb.z,p.kb.w};
        float qr[8] = {p.qa.x,p.qa.y,p.qa.z,p.qa.w,p.qb.x,p.qb.y,p.qb.z,p.qb.w};
        float d0 = 0.f, d1 = 0.f;
#pragma unroll
        for (int i = 0; i < 8; i += 2) {
            d0 = fmaf(S[i],   kr[i],   d0);
            d1 = fmaf(S[i+1], kr[i+1], d1);
        }
        float d = d0 + d1;
        d += __shfl_xor_sync(0xffffffffu, d, 1);
        d += __shfl_xor_sync(0xffffffffu, d, 2);
        d += __shfl_xor_sync(0xffffffffu, d, 4);
        float delta = p.b * (p.v - eg * d);
        float o0 = 0.f, o1 = 0.f;
#pragma unroll
        for (int i = 0; i < 8; i++) {
            S[i] = fmaf(S[i], eg, kr[i] * delta);
            if (i & 1) o1 = fmaf(S[i], qr[i], o1);
            else       o0 = fmaf(S[i], qr[i], o0);
        }
        float op = o0 + o1;
        op += __shfl_xor_sync(0xffffffffu, op, 1);
        op += __shfl_xor_sync(0xffffffffu, op, 2);
        op += __shfl_xor_sync(0xffffffffu, op, 4);
        if (rp == 0) obase[(size_t)t * VAL_DIM] = op * 0.125f;
    };

    ScanStep p0, p1, p2, p3;
    load(p0, 0); load(p1, 1); load(p2, 2); load(p3, 3);
    for (int t = 0; t < SS; t += 4) {
        compute(p0, t);   if (t + 4 < SS) load(p0, t + 4);
        compute(p1, t+1); if (t + 5 < SS) load(p1, t + 5);
        compute(p2, t+2); if (t + 6 < SS) load(p2, t + 6);
        compute(p3, t+3); if (t + 7 < SS) load(p3, t + 7);
    }
}

// ---------------- gated RMSNorm -> split-bf16 output ----------------
__global__ void gated_norm_kernel(const float* __restrict__ o,
                                  const float* __restrict__ ccat,
                                  const float* __restrict__ nw,
                                  __nv_bfloat16* __restrict__ hhl)
{
    int warp = threadIdx.x >> 5, lane = threadIdx.x & 31;
    size_t idx = (size_t)blockIdx.x * 8 + warp;
    int m  = (int)(idx >> 4);
    int hd = (int)(idx & 15);
    size_t base  = idx * DV;
    size_t zbase = (size_t)m * NCAT + 2048 + hd * DV;
    float o0 = o[base + lane],       o1 = o[base + lane + 32];
    float z0 = ccat[zbase + lane],   z1 = ccat[zbase + lane + 32];
    float h0 = o0 * (z0 / (1.f + expf(-z0)));
    float h1 = o1 * (z1 / (1.f + expf(-z1)));
    float ss = h0*h0 + h1*h1;
#pragma unroll
    for (int off = 16; off > 0; off >>= 1)
        ss += __shfl_xor_sync(0xffffffffu, ss, off);
    float scale = rsqrtf(ss * (1.f / DV) + 1e-6f);
    h0 *= scale * nw[lane];
    h1 *= scale * nw[lane + 32];

    int c0 = hd * 64 + lane;
    size_t b3 = (size_t)m * GK + c0;
    __nv_bfloat16 hi0 = __float2bfloat16_rn(h0);
    __nv_bfloat16 lo0 = __float2bfloat16_rn(h0 - __bfloat162float(hi0));
    __nv_bfloat16 hi1 = __float2bfloat16_rn(h1);
    __nv_bfloat16 lo1 = __float2bfloat16_rn(h1 - __bfloat162float(hi1));
    hhl[b3]            = hi0; hhl[b3 + 1024]      = hi0; hhl[b3 + 2048]      = lo0;
    hhl[b3 + 32]       = hi1; hhl[b3 + 32 + 1024] = hi1; hhl[b3 + 32 + 2048] = lo1;
}

// ---------------- driver ----------------
extern "C" void kernel_launch(void* const* d_in, const int* in_sizes, int n_in,
                              void* d_out, int out_size)
{
    const float* hidden  = (const float*)d_in[0];
    const float* W_qkv   = (const float*)d_in[1];
    const float* conv_w  = (const float*)d_in[2];
    const float* W_z     = (const float*)d_in[3];
    const float* W_b     = (const float*)d_in[4];
    const float* W_a     = (const float*)d_in[5];
    const float* dt_bias = (const float*)d_in[6];
    const float* A_log   = (const float*)d_in[7];
    const float* norm_w  = (const float*)d_in[8];
    const float* W_out   = (const float*)d_in[9];
    float* out = (float*)d_out;

    __nv_bfloat16 *ahl, *w16, *wo16, *hhl;
    float *ccat, *conv, *gg, *gb, *ov;
    cudaGetSymbolAddress((void**)&ahl,  g_ahl);
    cudaGetSymbolAddress((void**)&w16,  g_w16);
    cudaGetSymbolAddress((void**)&wo16, g_wo16);
    cudaGetSymbolAddress((void**)&hhl,  g_hhl);
    cudaGetSymbolAddress((void**)&ccat, g_ccat);
    cudaGetSymbolAddress((void**)&conv, g_conv);
    cudaGetSymbolAddress((void**)&gg,   g_gate);
    cudaGetSymbolAddress((void**)&gb,   g_beta);
    cudaGetSymbolAddress((void**)&ov,   g_o);

    // 0) split-bf16 conversions
    cvt_hidden_kernel<<<(MM*HH + 255) / 256, 256>>>(hidden, ahl);
    cvt_w_kernel<<<(NCAT*HH + 255) / 256, 256>>>(W_qkv, W_z, W_a, W_b, w16);
    cvt_wout_kernel<<<(HH*VAL_DIM + 255) / 256, 256>>>(W_out, wo16);
    // 1) Ccat = hidden @ Wcat^T  [8192, 3200]  via HMMA
    mma_gemm_kernel<<<dim3(NCAT/128, MM/128), 256>>>(ahl, w16, ccat, NCAT);
    // 2) depthwise causal conv + silu
    {
        size_t n = (size_t)MM * CONV_DIM;
        conv_silu_kernel<<<(unsigned)((n + 255) / 256), 256>>>(ccat, conv_w, conv);
    }
    // 3) gate / beta
    gate_kernel<<<(MM*NVH + 255) / 256, 256>>>(ccat, dt_bias, A_log, gg, gb);
    // 4) gated delta-rule scan
    scan_kernel<<<BB*NVH*4, 128>>>(conv, gg, gb, ov);
    // 5) gated RMSNorm -> split bf16
    gated_norm_kernel<<<(MM*NVH)/8, 256>>>(ov, ccat, norm_w, hhl);
    // 6) out = h @ W_out^T  [8192, 1024] via HMMA
    mma_gemm_kernel<<<dim3(HH/128, MM/128), 256>>>(hhl, wo16, out, HH);
}